// round 13
// baseline (speedup 1.0000x reference)
#include <cuda_runtime.h>
#include <math.h>
#include <stdint.h>

#define N_NODES 8192
#define F_IN    512
#define F_OUT   256
#define NEG_MASK (-9e15f)

__device__ float g_Wh[N_NODES * F_OUT];     // exact f32
__device__ float g_WhHp[N_NODES * F_OUT];   // tf32 hi, feature-pair packed (S + staging)
__device__ float g_WhTp[F_OUT * N_NODES];   // tf32 hi, transposed, key-pair packed + swizzled (PV)
__device__ float g_u[N_NODES], g_v[N_NODES], g_p[N_NODES], g_q[N_NODES];
__device__ float g_coef[4];

__device__ __forceinline__ uint32_t smem_u32(const void* p) {
    uint32_t a;
    asm("{ .reg .u64 t; cvta.to.shared.u64 t, %1; cvt.u32.u64 %0, t; }" : "=r"(a) : "l"(p));
    return a;
}
__device__ __forceinline__ uint32_t f2tf(float x) {
    uint32_t u; asm("cvt.rna.tf32.f32 %0, %1;" : "=r"(u) : "f"(x)); return u;
}
#define MMA(c, A, B) \
    asm volatile("mma.sync.aligned.m16n8k8.row.col.f32.tf32.tf32.f32 " \
        "{%0,%1,%2,%3},{%4,%5,%6,%7},{%8,%9},{%0,%1,%2,%3};" \
        : "+f"((c)[0]), "+f"((c)[1]), "+f"((c)[2]), "+f"((c)[3]) \
        : "r"((A)[0]), "r"((A)[1]), "r"((A)[2]), "r"((A)[3]), \
          "r"((B)[0]), "r"((B)[1]))
#define CP_ASYNC16(saddr, g) \
    asm volatile("cp.async.cg.shared.global [%0], [%1], 16;" :: "r"(saddr), "l"(g))
#define CP_COMMIT() asm volatile("cp.async.commit_group;")
#define CP_WAIT0()  asm volatile("cp.async.wait_group 0;")
#define CP_WAIT1()  asm volatile("cp.async.wait_group 1;")

// ---------------- kernel 1: softmax(Mui) ----------------
__global__ void mui_kernel(const float* __restrict__ Mui) {
    if (threadIdx.x == 0 && blockIdx.x == 0) {
        float m = -INFINITY;
        for (int i = 0; i < 6; i++) m = fmaxf(m, Mui[i]);
        float w[6], s = 0.f;
        for (int i = 0; i < 6; i++) { w[i] = expf(Mui[i] - m); s += w[i]; }
        float inv = 1.f / s;
        for (int i = 0; i < 6; i++) w[i] *= inv;
        g_coef[0] = w[0] + w[1] + w[2] + w[3];
        g_coef[1] = 0.5f * (w[0] + w[1]) + (w[2] + w[3]);
        g_coef[2] = 256.0f * w[4];
        g_coef[3] = 256.0f * w[5];
    }
}

// ---------------- kernel 2: Wh = h @ W; f32 + feature-pair-packed tf32 ----------------
__global__ __launch_bounds__(256) void wh_gemm(const float* __restrict__ h,
                                               const float* __restrict__ W) {
    __shared__ float sA[16][128];
    __shared__ float sB[16][128];
    const int tid = threadIdx.x, tx = tid & 15, ty = tid >> 4;
    const int n0 = blockIdx.x * 128, m0 = blockIdx.y * 128;
    float acc[8][8];
    #pragma unroll
    for (int i = 0; i < 8; i++)
        #pragma unroll
        for (int j = 0; j < 8; j++) acc[i][j] = 0.f;
    for (int k0 = 0; k0 < F_IN; k0 += 16) {
        #pragma unroll
        for (int l = 0; l < 2; l++) {
            int idx = tid + l * 256;
            int row = idx >> 2, kq = idx & 3;
            float4 a = *(const float4*)&h[(size_t)(m0 + row) * F_IN + k0 + kq * 4];
            sA[kq * 4 + 0][row] = a.x; sA[kq * 4 + 1][row] = a.y;
            sA[kq * 4 + 2][row] = a.z; sA[kq * 4 + 3][row] = a.w;
            int rowb = idx >> 5, cq = idx & 31;
            *(float4*)&sB[rowb][cq * 4] =
                *(const float4*)&W[(size_t)(k0 + rowb) * F_OUT + n0 + cq * 4];
        }
        __syncthreads();
        #pragma unroll
        for (int k = 0; k < 16; k++) {
            float a[8], b[8];
            *(float4*)(a) = *(float4*)&sA[k][ty * 8];
            *(float4*)(a + 4) = *(float4*)&sA[k][ty * 8 + 4];
            *(float4*)(b) = *(float4*)&sB[k][tx * 8];
            *(float4*)(b + 4) = *(float4*)&sB[k][tx * 8 + 4];
            #pragma unroll
            for (int i = 0; i < 8; i++)
                #pragma unroll
                for (int j = 0; j < 8; j++) acc[i][j] = fmaf(a[i], b[j], acc[i][j]);
        }
        __syncthreads();
    }
    #pragma unroll
    for (int i = 0; i < 8; i++) {
        size_t rowb = (size_t)(m0 + ty * 8 + i) * F_OUT;
        #pragma unroll
        for (int j4 = 0; j4 < 2; j4++) {
            size_t base = rowb + n0 + tx * 8 + j4 * 4;
            float4 v = *(float4*)&acc[i][j4 * 4];
            *(float4*)&g_Wh[base] = v;
            size_t pb = rowb + n0 + tx * 8;   // feature-pair pack: f -> (f&3)*2 + ((f>>2)&1)
            g_WhHp[pb + 0 * 2 + j4] = __uint_as_float(f2tf(v.x));
            g_WhHp[pb + 1 * 2 + j4] = __uint_as_float(f2tf(v.y));
            g_WhHp[pb + 2 * 2 + j4] = __uint_as_float(f2tf(v.z));
            g_WhHp[pb + 3 * 2 + j4] = __uint_as_float(f2tf(v.w));
        }
    }
}

// ---------------- kernel 3: per-node factors ----------------
__global__ void node_prep() {
    int i = blockIdx.x * blockDim.x + threadIdx.x;
    if (i < N_NODES) {
        float wh1 = g_Wh[(size_t)i * F_OUT + 1];
        float t1 = wh1 * wh1;
        g_u[i] = expf(0.5f * t1);
        g_v[i] = expf(t1);
        g_p[i] = g_coef[2] * expf(-0.5f * t1);
        g_q[i] = g_coef[3] * expf(-t1);
    }
}

// ---------------- kernel 3b: transpose + key-pair pack + swizzle ----------------
// g_WhTp[f][key-pairs]: key j -> u64col (j>>3)*4 + (j&3), elem (j>>2)&1;
// u64col low4 ^= (f&3)<<2 (bank swizzle, baked into gmem).
__global__ __launch_bounds__(256) void transpose_pack() {
    __shared__ float tile[64][33];
    const int f0 = blockIdx.x * 32, j0 = blockIdx.y * 64;
    const int tid = threadIdx.x;
    #pragma unroll
    for (int i = 0; i < 2; i++) {
        int idx = tid + i * 256;
        int row = idx >> 3, c4 = idx & 7;
        float4 a = *(const float4*)&g_Wh[(size_t)(j0 + row) * F_OUT + f0 + c4 * 4];
        tile[row][c4 * 4 + 0] = a.x; tile[row][c4 * 4 + 1] = a.y;
        tile[row][c4 * 4 + 2] = a.z; tile[row][c4 * 4 + 3] = a.w;
    }
    __syncthreads();
    #pragma unroll
    for (int i = 0; i < 4; i++) {
        int idx = tid + i * 256;
        int f = idx >> 5, p = idx & 31;
        int j = ((p >> 2) << 3) + (p & 3);
        int cs = p ^ ((f & 3) << 2);
        float2 o;
        o.x = __uint_as_float(f2tf(tile[j][f]));
        o.y = __uint_as_float(f2tf(tile[j + 4][f]));
        *(float2*)&g_WhTp[(size_t)(f0 + f) * N_NODES + j0 + cs * 2] = o;
    }
}

// ---------------- kernel 4: flash (packed frags both GEMMs, staggered cp.async) ----------------
#define SWP 264
#define OFF_WHJK 16896
#define OFF_WHJT 33792
#define OFF_P    50176
#define OFF_PART 54272
#define SMEM_FLASH (54528 * 4)

__global__ __launch_bounds__(512, 1) void flash_mma(const int* __restrict__ adj,
                                                    float* __restrict__ out) {
    extern __shared__ float sm[];
    const uint32_t sb = smem_u32(sm);
    float* sP = sm + OFF_P;
    float* sPart = sm + OFF_PART;

    const int tid = threadIdx.x, lane = tid & 31, wid = tid >> 5;
    const int wm = wid & 3, wn = wid >> 2;
    const int g = lane >> 2, t = lane & 3;
    const int i0 = blockIdx.x * 64;
    const int r0 = wm * 16 + g, r1 = r0 + 8;
    const int wn16 = wn * 16, wn64 = wn * 64;
    const int swz = (g & 3) << 2;

    // stage Whi (packed) once; prefetch K(0), T(0)
    for (int x = tid; x < 64 * 64; x += 512) {
        int row = x >> 6, c4 = x & 63;
        *(float4*)(sm + row * SWP + c4 * 4) =
            *(const float4*)(g_WhHp + (size_t)(i0 + row) * F_OUT + c4 * 4);
    }
    for (int x = tid; x < 64 * 64; x += 512) {
        int row = x >> 6, c4 = x & 63;
        CP_ASYNC16(sb + (OFF_WHJK + row * SWP + c4 * 4) * 4,
                   g_WhHp + (size_t)row * F_OUT + c4 * 4);
    }
    CP_COMMIT();
    for (int x = tid; x < 256 * 16; x += 512) {
        int row = x >> 4, ch = x & 15;
        CP_ASYNC16(sb + (OFF_WHJT + row * 64 + ch * 4) * 4,
                   g_WhTp + (size_t)row * N_NODES + ch * 4);
    }
    CP_COMMIT();

    const float cA = g_coef[0], cB = g_coef[1];
    const float pr0 = g_p[i0 + r0], qr0 = g_q[i0 + r0];
    const float pr1 = g_p[i0 + r1], qr1 = g_q[i0 + r1];
    const int* arow0 = adj + (size_t)(i0 + r0) * N_NODES;
    const int* arow1 = adj + (size_t)(i0 + r1) * N_NODES;

    float O[8][4];
    #pragma unroll
    for (int n = 0; n < 8; n++) { O[n][0] = O[n][1] = O[n][2] = O[n][3] = 0.f; }
    float lw0 = 0.f, lw1 = 0.f, m0 = -INFINITY, m1 = -INFINITY;

    const uint2* aRow0 = (const uint2*)sm + r0 * 132;
    const uint2* aRow1 = (const uint2*)sm + r1 * 132;
    const uint2* bBase = (const uint2*)(sm + OFF_WHJK);
    const uint2* pT    = (const uint2*)(sm + OFF_WHJT);
    const uint2* pPk   = (const uint2*)sP;

    for (int tt = 0; tt < 128; tt++) {
        CP_WAIT1();                 // K(tt) complete (T(tt) may be pending)
        __syncthreads();            // B-top: K(tt) (+Whi on tt=0) visible
        const int j0 = tt * 64;

        // ---- S = Whi . Whj^T (1xTF32, LDS.64 frags) ----
        float sS[2][4];
        sS[0][0] = sS[0][1] = sS[0][2] = sS[0][3] = 0.f;
        sS[1][0] = sS[1][1] = sS[1][2] = sS[1][3] = 0.f;
        const uint2* b0 = bBase + (wn16 + g) * 132;
        const uint2* b1 = bBase + (wn16 + 8 + g) * 132;
        #pragma unroll 8
        for (int ks = 0; ks < 32; ks++) {
            int po = ks * 4 + t;
            uint2 A0 = aRow0[po], A1 = aRow1[po];
            uint32_t A[4] = { A0.x, A1.x, A0.y, A1.y };
            uint2 Bv0 = b0[po];
            uint32_t B0[2] = { Bv0.x, Bv0.y };
            MMA(sS[0], A, B0);
            uint2 Bv1 = b1[po];
            uint32_t B1[2] = { Bv1.x, Bv1.y };
            MMA(sS[1], A, B1);
        }

        // ---- logits + row max ----
        float e[2][4];
        float rm0 = -INFINITY, rm1 = -INFINITY;
        #pragma unroll
        for (int nt = 0; nt < 2; nt++) {
            int jl = wn16 + nt * 8 + 2 * t;
            float2 uu = *(const float2*)(g_u + j0 + jl);
            float2 vv = *(const float2*)(g_v + j0 + jl);
            int2 a0 = *(const int2*)(arow0 + j0 + jl);
            int2 a1 = *(const int2*)(arow1 + j0 + jl);
            e[nt][0] = a0.x > 0 ? fmaf(cA, sS[nt][0], cB) + fmaf(pr0, uu.x, qr0 * vv.x) : NEG_MASK;
            e[nt][1] = a0.y > 0 ? fmaf(cA, sS[nt][1], cB) + fmaf(pr0, uu.y, qr0 * vv.y) : NEG_MASK;
            e[nt][2] = a1.x > 0 ? fmaf(cA, sS[nt][2], cB) + fmaf(pr1, uu.x, qr1 * vv.x) : NEG_MASK;
            e[nt][3] = a1.y > 0 ? fmaf(cA, sS[nt][3], cB) + fmaf(pr1, uu.y, qr1 * vv.y) : NEG_MASK;
            rm0 = fmaxf(rm0, fmaxf(e[nt][0], e[nt][1]));
            rm1 = fmaxf(rm1, fmaxf(e[nt][2], e[nt][3]));
        }
        rm0 = fmaxf(rm0, __shfl_xor_sync(~0u, rm0, 1));
        rm0 = fmaxf(rm0, __shfl_xor_sync(~0u, rm0, 2));
        rm1 = fmaxf(rm1, __shfl_xor_sync(~0u, rm1, 1));
        rm1 = fmaxf(rm1, __shfl_xor_sync(~0u, rm1, 2));
        if (t == 0) { sPart[wn * 64 + r0] = rm0; sPart[wn * 64 + r1] = rm1; }
        __syncthreads();            // B1: rowmax exchange; K(tt) reads done

        if (tt < 127) {             // prefetch K(tt+1) into the (now dead) K buffer
            for (int x = tid; x < 64 * 64; x += 512) {
                int row = x >> 6, c4 = x & 63;
                CP_ASYNC16(sb + (OFF_WHJK + row * SWP + c4 * 4) * 4,
                           g_WhHp + (size_t)(j0 + 64 + row) * F_OUT + c4 * 4);
            }
            CP_COMMIT();
        }

        float mn0 = fmaxf(fmaxf(sPart[r0], sPart[64 + r0]),
                          fmaxf(sPart[128 + r0], sPart[192 + r0]));
        float mn1 = fmaxf(fmaxf(sPart[r1], sPart[64 + r1]),
                          fmaxf(sPart[128 + r1], sPart[192 + r1]));
        mn0 = fmaxf(m0, mn0);
        mn1 = fmaxf(m1, mn1);
        float sc0 = __expf(m0 - mn0), sc1 = __expf(m1 - mn1);
        m0 = mn0; m1 = mn1;
        if (__ballot_sync(~0u, (sc0 < 1.f) | (sc1 < 1.f))) {
            lw0 *= sc0; lw1 *= sc1;
            #pragma unroll
            for (int n = 0; n < 8; n++) {
                O[n][0] *= sc0; O[n][1] *= sc0; O[n][2] *= sc1; O[n][3] *= sc1;
            }
        }
        // weights -> P (key-pair packed + swizzled)
        uint32_t* sPu = (uint32_t*)sP;
        #pragma unroll
        for (int nt = 0; nt < 2; nt++) {
            int jl = wn16 + nt * 8 + 2 * t;
            int p0i = ((jl >> 3) << 2) + (jl & 3), e0 = (jl >> 2) & 1;
            int j1 = jl + 1;
            int p1i = ((j1 >> 3) << 2) + (j1 & 3);
            int c0 = (((p0i ^ swz) << 1) + e0);
            int c1 = (((p1i ^ swz) << 1) + e0);
            uint32_t q0 = f2tf(__expf(e[nt][0] - m0));
            uint32_t q1 = f2tf(__expf(e[nt][1] - m0));
            uint32_t q2 = f2tf(__expf(e[nt][2] - m1));
            uint32_t q3 = f2tf(__expf(e[nt][3] - m1));
            lw0 += __uint_as_float(q0) + __uint_as_float(q1);
            lw1 += __uint_as_float(q2) + __uint_as_float(q3);
            sPu[r0 * 64 + c0] = q0;
            sPu[r0 * 64 + c1] = q1;
            sPu[r1 * 64 + c0] = q2;
            sPu[r1 * 64 + c1] = q3;
        }
        if (tt < 127) CP_WAIT1(); else CP_WAIT0();   // T(tt) complete
        __syncthreads();            // B2: P + T(tt) visible

        // ---- O += P . Whj (1xTF32, all LDS.64) ----
        #pragma unroll
        for (int ks = 0; ks < 8; ks++) {
            int c = (ks * 4 + t) ^ swz;
            uint2 A0 = pPk[r0 * 32 + c];
            uint2 A1 = pPk[r1 * 32 + c];
            uint32_t A[4] = { A0.x, A1.x, A0.y, A1.y };
            #pragma unroll
            for (int nt = 0; nt < 8; nt++) {
                uint2 Bv = pT[(wn64 + nt * 8 + g) * 32 + c];
                uint32_t B[2] = { Bv.x, Bv.y };
                MMA(O[nt], A, B);
            }
        }
        __syncthreads();            // B3: PV reads of T(tt)/P done

        if (tt < 127) {             // prefetch T(tt+1)
            for (int x = tid; x < 256 * 16; x += 512) {
                int row = x >> 4, ch = x & 15;
                CP_ASYNC16(sb + (OFF_WHJT + row * 64 + ch * 4) * 4,
                           g_WhTp + (size_t)row * N_NODES + j0 + 64 + ch * 4);
            }
            CP_COMMIT();
        }
    }

    // ---- epilogue ----
    lw0 += __shfl_xor_sync(~0u, lw0, 1); lw0 += __shfl_xor_sync(~0u, lw0, 2);
    lw1 += __shfl_xor_sync(~0u, lw1, 1); lw1 += __shfl_xor_sync(~0u, lw1, 2);
    if (t == 0) { sPart[wn * 64 + r0] = lw0; sPart[wn * 64 + r1] = lw1; }
    __syncthreads();
    float inv0 = 1.f / (sPart[r0] + sPart[64 + r0] + sPart[128 + r0] + sPart[192 + r0]);
    float inv1 = 1.f / (sPart[r1] + sPart[64 + r1] + sPart[128 + r1] + sPart[192 + r1]);
    #pragma unroll
    for (int nt = 0; nt < 8; nt++) {
        int col = wn64 + nt * 8 + 2 * t;
        float o0 = O[nt][0] * inv0, o1 = O[nt][1] * inv0;
        float o2 = O[nt][2] * inv1, o3 = O[nt][3] * inv1;
        o0 = o0 > 0.f ? o0 : expm1f(o0);
        o1 = o1 > 0.f ? o1 : expm1f(o1);
        o2 = o2 > 0.f ? o2 : expm1f(o2);
        o3 = o3 > 0.f ? o3 : expm1f(o3);
        *(float2*)(out + (size_t)(i0 + r0) * F_OUT + col) = make_float2(o0, o1);
        *(float2*)(out + (size_t)(i0 + r1) * F_OUT + col) = make_float2(o2, o3);
    }
}

// ---------------- launcher ----------------
extern "C" void kernel_launch(void* const* d_in, const int* in_sizes, int n_in,
                              void* d_out, int out_size) {
    const float* h   = (const float*)d_in[0];
    const float* W   = (const float*)d_in[1];
    const float* Mui = (const float*)d_in[2];
    const int*   adj = (const int*)d_in[3];
    float* out = (float*)d_out;
    (void)in_sizes; (void)n_in; (void)out_size;

    cudaFuncSetAttribute(flash_mma, cudaFuncAttributeMaxDynamicSharedMemorySize,
                         SMEM_FLASH);

    mui_kernel<<<1, 32>>>(Mui);
    wh_gemm<<<dim3(2, 64), 256>>>(h, W);
    node_prep<<<N_NODES / 256, 256>>>();
    transpose_pack<<<dim3(8, 128), 256>>>();
    flash_mma<<<N_NODES / 64, 512, SMEM_FLASH>>>(adj, out);
}

// round 14
// speedup vs baseline: 1.2839x; 1.2839x over previous
#include <cuda_runtime.h>
#include <math.h>
#include <stdint.h>
#include <cuda_bf16.h>

#define N_NODES 8192
#define F_IN    512
#define F_OUT   256
#define NEG_MASK (-9e15f)

__device__ float    g_Wh[N_NODES * F_OUT];            // exact f32
__device__ uint32_t g_WhBp[N_NODES * (F_OUT / 2)];    // bf16x2, frag-packed per node (S)
__device__ float    g_WhTp[F_OUT * N_NODES];          // tf32, transposed, key-pair packed (PV)
__device__ float g_u[N_NODES], g_v[N_NODES], g_p[N_NODES], g_q[N_NODES];
__device__ float g_coef[4];

__device__ __forceinline__ uint32_t smem_u32(const void* p) {
    uint32_t a;
    asm("{ .reg .u64 t; cvta.to.shared.u64 t, %1; cvt.u32.u64 %0, t; }" : "=r"(a) : "l"(p));
    return a;
}
__device__ __forceinline__ uint32_t f2tf(float x) {
    uint32_t u; asm("cvt.rna.tf32.f32 %0, %1;" : "=r"(u) : "f"(x)); return u;
}
__device__ __forceinline__ uint32_t pack_bf16(float lo, float hi) {
    uint32_t r; asm("cvt.rn.bf16x2.f32 %0, %1, %2;" : "=r"(r) : "f"(hi), "f"(lo)); return r;
}
#define MMA8(c, A, B) \
    asm volatile("mma.sync.aligned.m16n8k8.row.col.f32.tf32.tf32.f32 " \
        "{%0,%1,%2,%3},{%4,%5,%6,%7},{%8,%9},{%0,%1,%2,%3};" \
        : "+f"((c)[0]), "+f"((c)[1]), "+f"((c)[2]), "+f"((c)[3]) \
        : "r"((A)[0]), "r"((A)[1]), "r"((A)[2]), "r"((A)[3]), \
          "r"((B)[0]), "r"((B)[1]))
#define MMA16(c, A, B) \
    asm volatile("mma.sync.aligned.m16n8k16.row.col.f32.bf16.bf16.f32 " \
        "{%0,%1,%2,%3},{%4,%5,%6,%7},{%8,%9},{%0,%1,%2,%3};" \
        : "+f"((c)[0]), "+f"((c)[1]), "+f"((c)[2]), "+f"((c)[3]) \
        : "r"((A)[0]), "r"((A)[1]), "r"((A)[2]), "r"((A)[3]), \
          "r"((B)[0]), "r"((B)[1]))
#define CP_ASYNC16(saddr, g) \
    asm volatile("cp.async.cg.shared.global [%0], [%1], 16;" :: "r"(saddr), "l"(g))
#define CP_COMMIT() asm volatile("cp.async.commit_group;")
#define CP_WAITG(n) asm volatile("cp.async.wait_group %0;" :: "n"(n))

// ---------------- kernel 1: softmax(Mui) ----------------
__global__ void mui_kernel(const float* __restrict__ Mui) {
    if (threadIdx.x == 0 && blockIdx.x == 0) {
        float m = -INFINITY;
        for (int i = 0; i < 6; i++) m = fmaxf(m, Mui[i]);
        float w[6], s = 0.f;
        for (int i = 0; i < 6; i++) { w[i] = expf(Mui[i] - m); s += w[i]; }
        float inv = 1.f / s;
        for (int i = 0; i < 6; i++) w[i] *= inv;
        g_coef[0] = w[0] + w[1] + w[2] + w[3];
        g_coef[1] = 0.5f * (w[0] + w[1]) + (w[2] + w[3]);
        g_coef[2] = 256.0f * w[4];
        g_coef[3] = 256.0f * w[5];
    }
}

// ---------------- kernel 2: Wh = h @ W; emit f32 + bf16-frag-packed ----------------
__global__ __launch_bounds__(256) void wh_gemm(const float* __restrict__ h,
                                               const float* __restrict__ W) {
    __shared__ float sA[16][128];
    __shared__ float sB[16][128];
    const int tid = threadIdx.x, tx = tid & 15, ty = tid >> 4;
    const int n0 = blockIdx.x * 128, m0 = blockIdx.y * 128;
    float acc[8][8];
    #pragma unroll
    for (int i = 0; i < 8; i++)
        #pragma unroll
        for (int j = 0; j < 8; j++) acc[i][j] = 0.f;
    for (int k0 = 0; k0 < F_IN; k0 += 16) {
        #pragma unroll
        for (int l = 0; l < 2; l++) {
            int idx = tid + l * 256;
            int row = idx >> 2, kq = idx & 3;
            float4 a = *(const float4*)&h[(size_t)(m0 + row) * F_IN + k0 + kq * 4];
            sA[kq * 4 + 0][row] = a.x; sA[kq * 4 + 1][row] = a.y;
            sA[kq * 4 + 2][row] = a.z; sA[kq * 4 + 3][row] = a.w;
            int rowb = idx >> 5, cq = idx & 31;
            *(float4*)&sB[rowb][cq * 4] =
                *(const float4*)&W[(size_t)(k0 + rowb) * F_OUT + n0 + cq * 4];
        }
        __syncthreads();
        #pragma unroll
        for (int k = 0; k < 16; k++) {
            float a[8], b[8];
            *(float4*)(a) = *(float4*)&sA[k][ty * 8];
            *(float4*)(a + 4) = *(float4*)&sA[k][ty * 8 + 4];
            *(float4*)(b) = *(float4*)&sB[k][tx * 8];
            *(float4*)(b + 4) = *(float4*)&sB[k][tx * 8 + 4];
            #pragma unroll
            for (int i = 0; i < 8; i++)
                #pragma unroll
                for (int j = 0; j < 8; j++) acc[i][j] = fmaf(a[i], b[j], acc[i][j]);
        }
        __syncthreads();
    }
    const int base = n0 + tx * 8;
    #pragma unroll
    for (int i = 0; i < 8; i++) {
        size_t rw = (size_t)(m0 + ty * 8 + i);
        *(float4*)&g_Wh[rw * F_OUT + base]     = *(float4*)&acc[i][0];
        *(float4*)&g_Wh[rw * F_OUT + base + 4] = *(float4*)&acc[i][4];
        // bf16 frag pack: word of feats (f, f+1); within 16-feat group, word wl ->
        // pos = (wl&3)*2 + (wl>>2)  (puts (wl, wl+4) adjacent for LDS.64 frags)
        #pragma unroll
        for (int w2 = 0; w2 < 4; w2++) {
            int f = base + 2 * w2;
            int gi = f >> 4, wl = (f >> 1) & 7;
            int pos = (wl & 3) * 2 + (wl >> 2);
            g_WhBp[rw * 128 + gi * 8 + pos] = pack_bf16(acc[i][2 * w2], acc[i][2 * w2 + 1]);
        }
    }
}

// ---------------- kernel 3: per-node factors ----------------
__global__ void node_prep() {
    int i = blockIdx.x * blockDim.x + threadIdx.x;
    if (i < N_NODES) {
        float wh1 = g_Wh[(size_t)i * F_OUT + 1];
        float t1 = wh1 * wh1;
        g_u[i] = expf(0.5f * t1);
        g_v[i] = expf(t1);
        g_p[i] = g_coef[2] * expf(-0.5f * t1);
        g_q[i] = g_coef[3] * expf(-t1);
    }
}

// ---------------- kernel 3b: transpose + key-pair pack (tf32, for PV) ----------------
__global__ __launch_bounds__(256) void transpose_pack() {
    __shared__ float tile[64][33];
    const int f0 = blockIdx.x * 32, j0 = blockIdx.y * 64;
    const int tid = threadIdx.x;
    #pragma unroll
    for (int i = 0; i < 2; i++) {
        int idx = tid + i * 256;
        int row = idx >> 3, c4 = idx & 7;
        float4 a = *(const float4*)&g_Wh[(size_t)(j0 + row) * F_OUT + f0 + c4 * 4];
        tile[row][c4 * 4 + 0] = a.x; tile[row][c4 * 4 + 1] = a.y;
        tile[row][c4 * 4 + 2] = a.z; tile[row][c4 * 4 + 3] = a.w;
    }
    __syncthreads();
    #pragma unroll
    for (int i = 0; i < 4; i++) {
        int idx = tid + i * 256;
        int f = idx >> 5, p = idx & 31;           // word p holds keys (k, k+4)
        int k = ((p >> 2) << 3) + (p & 3);
        float2 o;
        o.x = __uint_as_float(f2tf(tile[k][f]));
        o.y = __uint_as_float(f2tf(tile[k + 4][f]));
        *(float2*)&g_WhTp[(size_t)(f0 + f) * N_NODES + j0 + p * 2] = o;
    }
}

// ---------------- kernel 4: flash (bf16 S, tf32 PV, conflict-free strides) ----------------
// u32-unit smem offsets; all u64 strides == 4 (mod 16) -> conflict-free frag LDS.64
#define OFF_WHI  0        // 64 x 136 u32 (bf16 tile, u64 stride 68)
#define OFF_K0   8704
#define OFF_K1   17408
#define OFF_T    26112    // 256 x 72 f32 (u64 stride 36)
#define OFF_P    44544    // 64 x 72 f32
#define OFF_PART 49152    // 256 f32
#define SMEM_FLASH (49408 * 4)

__global__ __launch_bounds__(512, 1) void flash_mma(const int* __restrict__ adj,
                                                    float* __restrict__ out) {
    extern __shared__ float sm[];
    uint32_t* smu = (uint32_t*)sm;
    const uint32_t sb = smem_u32(sm);
    float* sPart = sm + OFF_PART;

    const int tid = threadIdx.x, lane = tid & 31, wid = tid >> 5;
    const int wm = wid & 3, wn = wid >> 2;
    const int g = lane >> 2, t = lane & 3;
    const int i0 = blockIdx.x * 64;
    const int r0 = wm * 16 + g, r1 = r0 + 8;
    const int wn16 = wn * 16, wn64 = wn * 64;

    // stage Whi (bf16 packed)
    for (int x = tid; x < 64 * 32; x += 512) {
        int row = x >> 5, c = x & 31;
        *(uint4*)(smu + OFF_WHI + row * 136 + c * 4) =
            *(const uint4*)(g_WhBp + (size_t)(i0 + row) * 128 + c * 4);
    }
    // prefetch K(0), T(0)
    for (int x = tid; x < 64 * 32; x += 512) {
        int row = x >> 5, c = x & 31;
        CP_ASYNC16(sb + (OFF_K0 + row * 136 + c * 4) * 4,
                   g_WhBp + (size_t)row * 128 + c * 4);
    }
    CP_COMMIT();
    for (int x = tid; x < 256 * 16; x += 512) {
        int rf = x >> 4, c = x & 15;
        CP_ASYNC16(sb + (OFF_T + rf * 72 + c * 4) * 4,
                   g_WhTp + (size_t)rf * N_NODES + c * 4);
    }
    CP_COMMIT();

    const float cA = g_coef[0], cB = g_coef[1];
    const float pr0 = g_p[i0 + r0], qr0 = g_q[i0 + r0];
    const float pr1 = g_p[i0 + r1], qr1 = g_q[i0 + r1];
    const int* arow0 = adj + (size_t)(i0 + r0) * N_NODES;
    const int* arow1 = adj + (size_t)(i0 + r1) * N_NODES;
    const int jl0 = wn16 + 2 * t, jl1 = wn16 + 8 + 2 * t;

    // adj prefetch registers (tile 0)
    int2 pa[4];
    pa[0] = *(const int2*)(arow0 + jl0);
    pa[1] = *(const int2*)(arow0 + jl1);
    pa[2] = *(const int2*)(arow1 + jl0);
    pa[3] = *(const int2*)(arow1 + jl1);

    float O[8][4];
    #pragma unroll
    for (int n = 0; n < 8; n++) { O[n][0] = O[n][1] = O[n][2] = O[n][3] = 0.f; }
    float lw0 = 0.f, lw1 = 0.f, m0 = -INFINITY, m1 = -INFINITY;

    const uint2* aR0 = (const uint2*)smu + (OFF_WHI >> 1) + r0 * 68;
    const uint2* aR1 = (const uint2*)smu + (OFF_WHI >> 1) + r1 * 68;
    const uint2* pPk = (const uint2*)(smu + OFF_P);
    const uint2* pT  = (const uint2*)(smu + OFF_T);
    uint32_t* sPu = smu + OFF_P;

    for (int tt = 0; tt < 128; tt++) {
        const int j0 = tt * 64;
        const int jn = ((tt + 1) & 127) * 64;
        {   // prefetch K(tt+1) into the other buffer
            int koff = ((tt + 1) & 1) ? OFF_K1 : OFF_K0;
            for (int x = tid; x < 64 * 32; x += 512) {
                int row = x >> 5, c = x & 31;
                CP_ASYNC16(sb + (koff + row * 136 + c * 4) * 4,
                           g_WhBp + (size_t)(jn + row) * 128 + c * 4);
            }
            CP_COMMIT();
        }
        CP_WAITG(2);
        __syncthreads();                       // B0: K(tt) visible

        // prefetch adj(tt+1) into registers
        int2 na0 = *(const int2*)(arow0 + jn + jl0);
        int2 na1 = *(const int2*)(arow0 + jn + jl1);
        int2 na2 = *(const int2*)(arow1 + jn + jl0);
        int2 na3 = *(const int2*)(arow1 + jn + jl1);

        // ---- S = Whi . Whj^T (bf16 m16n8k16) ----
        float sS[2][4];
        sS[0][0] = sS[0][1] = sS[0][2] = sS[0][3] = 0.f;
        sS[1][0] = sS[1][1] = sS[1][2] = sS[1][3] = 0.f;
        const uint2* bK = (const uint2*)smu + (((tt & 1) ? OFF_K1 : OFF_K0) >> 1);
        const uint2* b0 = bK + (wn16 + g) * 68;
        const uint2* b1 = bK + (wn16 + 8 + g) * 68;
        #pragma unroll
        for (int gi = 0; gi < 16; gi++) {
            int o = gi * 4 + t;
            uint2 A0 = aR0[o], A1 = aR1[o];
            uint32_t A[4] = { A0.x, A1.x, A0.y, A1.y };
            uint2 Bv0 = b0[o];
            uint32_t B0[2] = { Bv0.x, Bv0.y };
            MMA16(sS[0], A, B0);
            uint2 Bv1 = b1[o];
            uint32_t B1[2] = { Bv1.x, Bv1.y };
            MMA16(sS[1], A, B1);
        }

        // ---- logits + row max ----
        float e[2][4];
        float rm0 = -INFINITY, rm1 = -INFINITY;
        #pragma unroll
        for (int nt = 0; nt < 2; nt++) {
            int jl = wn16 + nt * 8 + 2 * t;
            float2 uu = *(const float2*)(g_u + j0 + jl);
            float2 vv = *(const float2*)(g_v + j0 + jl);
            int2 a0 = pa[nt], a1 = pa[2 + nt];
            e[nt][0] = a0.x > 0 ? fmaf(cA, sS[nt][0], cB) + fmaf(pr0, uu.x, qr0 * vv.x) : NEG_MASK;
            e[nt][1] = a0.y > 0 ? fmaf(cA, sS[nt][1], cB) + fmaf(pr0, uu.y, qr0 * vv.y) : NEG_MASK;
            e[nt][2] = a1.x > 0 ? fmaf(cA, sS[nt][2], cB) + fmaf(pr1, uu.x, qr1 * vv.x) : NEG_MASK;
            e[nt][3] = a1.y > 0 ? fmaf(cA, sS[nt][3], cB) + fmaf(pr1, uu.y, qr1 * vv.y) : NEG_MASK;
            rm0 = fmaxf(rm0, fmaxf(e[nt][0], e[nt][1]));
            rm1 = fmaxf(rm1, fmaxf(e[nt][2], e[nt][3]));
        }
        pa[0] = na0; pa[1] = na1; pa[2] = na2; pa[3] = na3;
        rm0 = fmaxf(rm0, __shfl_xor_sync(~0u, rm0, 1));
        rm0 = fmaxf(rm0, __shfl_xor_sync(~0u, rm0, 2));
        rm1 = fmaxf(rm1, __shfl_xor_sync(~0u, rm1, 1));
        rm1 = fmaxf(rm1, __shfl_xor_sync(~0u, rm1, 2));
        if (t == 0) { sPart[wn * 64 + r0] = rm0; sPart[wn * 64 + r1] = rm1; }
        __syncthreads();                       // B1

        float mn0 = fmaxf(fmaxf(sPart[r0], sPart[64 + r0]),
                          fmaxf(sPart[128 + r0], sPart[192 + r0]));
        float mn1 = fmaxf(fmaxf(sPart[r1], sPart[64 + r1]),
                          fmaxf(sPart[128 + r1], sPart[192 + r1]));
        mn0 = fmaxf(m0, mn0);
        mn1 = fmaxf(m1, mn1);
        float sc0 = __expf(m0 - mn0), sc1 = __expf(m1 - mn1);
        m0 = mn0; m1 = mn1;
        if (__ballot_sync(~0u, (sc0 < 1.f) | (sc1 < 1.f))) {
            lw0 *= sc0; lw1 *= sc1;
            #pragma unroll
            for (int n = 0; n < 8; n++) {
                O[n][0] *= sc0; O[n][1] *= sc0; O[n][2] *= sc1; O[n][3] *= sc1;
            }
        }
        // weights -> P (key-pair packed, stride 72 f32)
        #pragma unroll
        for (int nt = 0; nt < 2; nt++) {
            int jl = wn16 + nt * 8 + 2 * t;
            int w = (jl & 3) + ((jl >> 3) << 2);
            int eb = (jl >> 2) & 1;
            int ix = w * 2 + eb;
            uint32_t q0 = f2tf(__expf(e[nt][0] - m0));
            uint32_t q1 = f2tf(__expf(e[nt][1] - m0));
            uint32_t q2 = f2tf(__expf(e[nt][2] - m1));
            uint32_t q3 = f2tf(__expf(e[nt][3] - m1));
            lw0 += __uint_as_float(q0) + __uint_as_float(q1);
            lw1 += __uint_as_float(q2) + __uint_as_float(q3);
            sPu[r0 * 72 + ix] = q0;
            sPu[r0 * 72 + ix + 2] = q1;
            sPu[r1 * 72 + ix] = q2;
            sPu[r1 * 72 + ix + 2] = q3;
        }
        CP_WAITG(1);
        __syncthreads();                       // B2: P + T(tt) visible

        // ---- O += P . Whj (tf32, all LDS.64, conflict-free) ----
        #pragma unroll
        for (int ks = 0; ks < 8; ks++) {
            int o = ks * 4 + t;
            uint2 A0 = pPk[r0 * 36 + o];
            uint2 A1 = pPk[r1 * 36 + o];
            uint32_t A[4] = { A0.x, A1.x, A0.y, A1.y };
            #pragma unroll
            for (int nt = 0; nt < 8; nt++) {
                uint2 Bv = pT[(wn64 + nt * 8 + g) * 36 + o];
                uint32_t B[2] = { Bv.x, Bv.y };
                MMA8(O[nt], A, B);
            }
        }
        __syncthreads();                       // B3: PV reads done

        {   // prefetch T(tt+1)
            for (int x = tid; x < 256 * 16; x += 512) {
                int rf = x >> 4, c = x & 15;
                CP_ASYNC16(sb + (OFF_T + rf * 72 + c * 4) * 4,
                           g_WhTp + (size_t)rf * N_NODES + jn + c * 4);
            }
            CP_COMMIT();
        }
    }

    // ---- epilogue ----
    lw0 += __shfl_xor_sync(~0u, lw0, 1); lw0 += __shfl_xor_sync(~0u, lw0, 2);
    lw1 += __shfl_xor_sync(~0u, lw1, 1); lw1 += __shfl_xor_sync(~0u, lw1, 2);
    if (t == 0) { sPart[wn * 64 + r0] = lw0; sPart[wn * 64 + r1] = lw1; }
    __syncthreads();
    float inv0 = 1.f / (sPart[r0] + sPart[64 + r0] + sPart[128 + r0] + sPart[192 + r0]);
    float inv1 = 1.f / (sPart[r1] + sPart[64 + r1] + sPart[128 + r1] + sPart[192 + r1]);
    #pragma unroll
    for (int nt = 0; nt < 8; nt++) {
        int col = wn64 + nt * 8 + 2 * t;
        float o0 = O[nt][0] * inv0, o1 = O[nt][1] * inv0;
        float o2 = O[nt][2] * inv1, o3 = O[nt][3] * inv1;
        o0 = o0 > 0.f ? o0 : expm1f(o0);
        o1 = o1 > 0.f ? o1 : expm1f(o1);
        o2 = o2 > 0.f ? o2 : expm1f(o2);
        o3 = o3 > 0.f ? o3 : expm1f(o3);
        *(float2*)(out + (size_t)(i0 + r0) * F_OUT + col) = make_float2(o0, o1);
        *(float2*)(out + (size_t)(i0 + r1) * F_OUT + col) = make_float2(o2, o3);
    }
}

// ---------------- launcher ----------------
extern "C" void kernel_launch(void* const* d_in, const int* in_sizes, int n_in,
                              void* d_out, int out_size) {
    const float* h   = (const float*)d_in[0];
    const float* W   = (const float*)d_in[1];
    const float* Mui = (const float*)d_in[2];
    const int*   adj = (const int*)d_in[3];
    float* out = (float*)d_out;
    (void)in_sizes; (void)n_in; (void)out_size;

    cudaFuncSetAttribute(flash_mma, cudaFuncAttributeMaxDynamicSharedMemorySize,
                         SMEM_FLASH);

    mui_kernel<<<1, 32>>>(Mui);
    wh_gemm<<<dim3(2, 64), 256>>>(h, W);
    node_prep<<<N_NODES / 256, 256>>>();
    transpose_pack<<<dim3(8, 128), 256>>>();
    flash_mma<<<N_NODES / 64, 512, SMEM_FLASH>>>(adj, out);
}

// round 15
// speedup vs baseline: 1.3550x; 1.0554x over previous
#include <cuda_runtime.h>
#include <math.h>
#include <stdint.h>
#include <cuda_bf16.h>

#define N_NODES 8192
#define F_IN    512
#define F_OUT   256
#define NEG_MASK (-9e15f)

__device__ float    g_Wh[N_NODES * F_OUT];           // exact f32
__device__ uint32_t g_WhBp[N_NODES * (F_OUT / 2)];   // bf16x2 frag-packed (S)
__device__ uint4    g_WhT2[F_OUT * 2048];            // V^T bf16 hi/lo, u128 frag-packed (PV)
__device__ float g_u[N_NODES], g_v[N_NODES], g_p[N_NODES], g_q[N_NODES];
__device__ float g_coef[4];

__device__ __forceinline__ uint32_t smem_u32(const void* p) {
    uint32_t a;
    asm("{ .reg .u64 t; cvta.to.shared.u64 t, %1; cvt.u32.u64 %0, t; }" : "=r"(a) : "l"(p));
    return a;
}
__device__ __forceinline__ uint32_t pack_bf16(float lo, float hi) {
    uint32_t r; asm("cvt.rn.bf16x2.f32 %0, %1, %2;" : "=r"(r) : "f"(hi), "f"(lo)); return r;
}
#define MMA16(c, A, B) \
    asm volatile("mma.sync.aligned.m16n8k16.row.col.f32.bf16.bf16.f32 " \
        "{%0,%1,%2,%3},{%4,%5,%6,%7},{%8,%9},{%0,%1,%2,%3};" \
        : "+f"((c)[0]), "+f"((c)[1]), "+f"((c)[2]), "+f"((c)[3]) \
        : "r"((A)[0]), "r"((A)[1]), "r"((A)[2]), "r"((A)[3]), \
          "r"((B)[0]), "r"((B)[1]))
#define CP_ASYNC16(saddr, g) \
    asm volatile("cp.async.cg.shared.global [%0], [%1], 16;" :: "r"(saddr), "l"(g))
#define CP_COMMIT() asm volatile("cp.async.commit_group;")
#define CP_WAITG(n) asm volatile("cp.async.wait_group %0;" :: "n"(n))

// ---------------- kernel 1: softmax(Mui) ----------------
__global__ void mui_kernel(const float* __restrict__ Mui) {
    if (threadIdx.x == 0 && blockIdx.x == 0) {
        float m = -INFINITY;
        for (int i = 0; i < 6; i++) m = fmaxf(m, Mui[i]);
        float w[6], s = 0.f;
        for (int i = 0; i < 6; i++) { w[i] = expf(Mui[i] - m); s += w[i]; }
        float inv = 1.f / s;
        for (int i = 0; i < 6; i++) w[i] *= inv;
        g_coef[0] = w[0] + w[1] + w[2] + w[3];
        g_coef[1] = 0.5f * (w[0] + w[1]) + (w[2] + w[3]);
        g_coef[2] = 256.0f * w[4];
        g_coef[3] = 256.0f * w[5];
    }
}

// ---------------- kernel 2: Wh = h @ W; f32 + bf16 frag-packed ----------------
__global__ __launch_bounds__(256) void wh_gemm(const float* __restrict__ h,
                                               const float* __restrict__ W) {
    __shared__ float sA[16][128];
    __shared__ float sB[16][128];
    const int tid = threadIdx.x, tx = tid & 15, ty = tid >> 4;
    const int n0 = blockIdx.x * 128, m0 = blockIdx.y * 128;
    float acc[8][8];
    #pragma unroll
    for (int i = 0; i < 8; i++)
        #pragma unroll
        for (int j = 0; j < 8; j++) acc[i][j] = 0.f;
    for (int k0 = 0; k0 < F_IN; k0 += 16) {
        #pragma unroll
        for (int l = 0; l < 2; l++) {
            int idx = tid + l * 256;
            int row = idx >> 2, kq = idx & 3;
            float4 a = *(const float4*)&h[(size_t)(m0 + row) * F_IN + k0 + kq * 4];
            sA[kq * 4 + 0][row] = a.x; sA[kq * 4 + 1][row] = a.y;
            sA[kq * 4 + 2][row] = a.z; sA[kq * 4 + 3][row] = a.w;
            int rowb = idx >> 5, cq = idx & 31;
            *(float4*)&sB[rowb][cq * 4] =
                *(const float4*)&W[(size_t)(k0 + rowb) * F_OUT + n0 + cq * 4];
        }
        __syncthreads();
        #pragma unroll
        for (int k = 0; k < 16; k++) {
            float a[8], b[8];
            *(float4*)(a) = *(float4*)&sA[k][ty * 8];
            *(float4*)(a + 4) = *(float4*)&sA[k][ty * 8 + 4];
            *(float4*)(b) = *(float4*)&sB[k][tx * 8];
            *(float4*)(b + 4) = *(float4*)&sB[k][tx * 8 + 4];
            #pragma unroll
            for (int i = 0; i < 8; i++)
                #pragma unroll
                for (int j = 0; j < 8; j++) acc[i][j] = fmaf(a[i], b[j], acc[i][j]);
        }
        __syncthreads();
    }
    const int base = n0 + tx * 8;
    #pragma unroll
    for (int i = 0; i < 8; i++) {
        size_t rw = (size_t)(m0 + ty * 8 + i);
        *(float4*)&g_Wh[rw * F_OUT + base]     = *(float4*)&acc[i][0];
        *(float4*)&g_Wh[rw * F_OUT + base + 4] = *(float4*)&acc[i][4];
        #pragma unroll
        for (int w2 = 0; w2 < 4; w2++) {
            int f = base + 2 * w2;
            int gi = f >> 4, wl = (f >> 1) & 7;
            int pos = (wl & 3) * 2 + (wl >> 2);
            g_WhBp[rw * 128 + gi * 8 + pos] = pack_bf16(acc[i][2 * w2], acc[i][2 * w2 + 1]);
        }
    }
}

// ---------------- kernel 3: per-node factors ----------------
__global__ void node_prep() {
    int i = blockIdx.x * blockDim.x + threadIdx.x;
    if (i < N_NODES) {
        float wh1 = g_Wh[(size_t)i * F_OUT + 1];
        float t1 = wh1 * wh1;
        g_u[i] = expf(0.5f * t1);
        g_v[i] = expf(t1);
        g_p[i] = g_coef[2] * expf(-0.5f * t1);
        g_q[i] = g_coef[3] * expf(-t1);
    }
}

// ---------------- kernel 3b: V^T bf16 hi/lo, u128 frag-packed ----------------
// For feature f, 16-key group: thread-word t u128 = {hi(k=2t..), hi(k=2t+8..), lo(..), lo(..)}
__global__ __launch_bounds__(256) void transpose_pack() {
    __shared__ float tile[64][33];
    const int f0 = blockIdx.x * 32, j0 = blockIdx.y * 64;
    const int tid = threadIdx.x;
    #pragma unroll
    for (int i = 0; i < 2; i++) {
        int idx = tid + i * 256;
        int row = idx >> 3, c4 = idx & 7;
        float4 a = *(const float4*)&g_Wh[(size_t)(j0 + row) * F_OUT + f0 + c4 * 4];
        tile[row][c4 * 4 + 0] = a.x; tile[row][c4 * 4 + 1] = a.y;
        tile[row][c4 * 4 + 2] = a.z; tile[row][c4 * 4 + 3] = a.w;
    }
    __syncthreads();
    #pragma unroll
    for (int i = 0; i < 2; i++) {
        int idx = tid + i * 256;
        int f = idx >> 4, gi = (idx >> 2) & 3, t = idx & 3;
        int k0 = gi * 16 + 2 * t;
        float e00 = tile[k0][f],     e01 = tile[k0 + 1][f];
        float e10 = tile[k0 + 8][f], e11 = tile[k0 + 9][f];
        uint32_t h0 = pack_bf16(e00, e01);
        uint32_t h1 = pack_bf16(e10, e11);
        float r00 = e00 - __uint_as_float(h0 << 16);
        float r01 = e01 - __uint_as_float(h0 & 0xffff0000u);
        float r10 = e10 - __uint_as_float(h1 << 16);
        float r11 = e11 - __uint_as_float(h1 & 0xffff0000u);
        uint4 o = make_uint4(h0, h1, pack_bf16(r00, r01), pack_bf16(r10, r11));
        g_WhT2[(size_t)(f0 + f) * 2048 + ((j0 >> 4) + gi) * 4 + t] = o;
    }
}

// ---------------- kernel 4: flash (bf16 S, bf16 hi/lo PV) ----------------
// S warps: wm=wid&3 (16 rows), wn=wid>>2 (16 S-cols).
// PV warps: wmO=wid&1 (32 rows), wnO=wid>>1 (32 O-cols).
#define OFF_WHI  0        // 64 x 136 u32
#define OFF_K0   8704
#define OFF_K1   17408
#define OFF_T    26112    // 256 x 80 u32 (u128 stride 20)
#define OFF_P    46592    // 64 x 40 u32 (bf16x2, u64 stride 20)
#define OFF_PART 49152    // 256 f32
#define OFF_SC   49408    // 64 f32
#define SMEM_FLASH (49472 * 4)

__global__ __launch_bounds__(512, 1) void flash_mma(const int* __restrict__ adj,
                                                    float* __restrict__ out) {
    extern __shared__ float sm[];
    uint32_t* smu = (uint32_t*)sm;
    const uint32_t sb = smem_u32(sm);
    float* sPart = sm + OFF_PART;
    float* sSc   = sm + OFF_SC;

    const int tid = threadIdx.x, lane = tid & 31, wid = tid >> 5;
    const int wm = wid & 3, wn = wid >> 2;            // S mapping
    const int wmO = wid & 1, wnO = wid >> 1;          // PV mapping
    const int g = lane >> 2, t = lane & 3;
    const int i0 = blockIdx.x * 64;
    const int r0 = wm * 16 + g, r1 = r0 + 8;
    const int wn16 = wn * 16;

    // stage Whi (bf16 packed)
    for (int x = tid; x < 64 * 32; x += 512) {
        int row = x >> 5, c = x & 31;
        *(uint4*)(smu + OFF_WHI + row * 136 + c * 4) =
            *(const uint4*)(g_WhBp + (size_t)(i0 + row) * 128 + c * 4);
    }
    // prefetch K(0), T(0)
    for (int x = tid; x < 64 * 32; x += 512) {
        int row = x >> 5, c = x & 31;
        CP_ASYNC16(sb + (OFF_K0 + row * 136 + c * 4) * 4,
                   g_WhBp + (size_t)row * 128 + c * 4);
    }
    CP_COMMIT();
    for (int x = tid; x < 256 * 16; x += 512) {
        int f = x >> 4, q = x & 15;
        CP_ASYNC16(sb + (OFF_T + f * 80 + q * 4) * 4,
                   (const char*)(g_WhT2 + (size_t)f * 2048 + q));
    }
    CP_COMMIT();

    const float cA = g_coef[0], cB = g_coef[1];
    const float pr0 = g_p[i0 + r0], qr0 = g_q[i0 + r0];
    const float pr1 = g_p[i0 + r1], qr1 = g_q[i0 + r1];
    const int* arow0 = adj + (size_t)(i0 + r0) * N_NODES;
    const int* arow1 = adj + (size_t)(i0 + r1) * N_NODES;
    const int jl0 = wn16 + 2 * t, jl1 = wn16 + 8 + 2 * t;

    int2 pa[4];
    pa[0] = *(const int2*)(arow0 + jl0);
    pa[1] = *(const int2*)(arow0 + jl1);
    pa[2] = *(const int2*)(arow1 + jl0);
    pa[3] = *(const int2*)(arow1 + jl1);

    float O[2][4][4];
    #pragma unroll
    for (int mt = 0; mt < 2; mt++)
        #pragma unroll
        for (int nt = 0; nt < 4; nt++)
            #pragma unroll
            for (int c = 0; c < 4; c++) O[mt][nt][c] = 0.f;
    float lw0 = 0.f, lw1 = 0.f, m0 = -INFINITY, m1 = -INFINITY;

    const uint2* aR0 = (const uint2*)smu + (OFF_WHI >> 1) + r0 * 68;
    const uint2* aR1 = (const uint2*)smu + (OFF_WHI >> 1) + r1 * 68;
    const uint2* pP2 = (const uint2*)(smu + OFF_P);
    const uint4* pT4 = (const uint4*)(smu + OFF_T);
    uint32_t* sPu = smu + OFF_P;

    for (int tt = 0; tt < 128; tt++) {
        const int j0 = tt * 64;
        const int jn = ((tt + 1) & 127) * 64;
        {   // prefetch K(tt+1)
            int koff = ((tt + 1) & 1) ? OFF_K1 : OFF_K0;
            for (int x = tid; x < 64 * 32; x += 512) {
                int row = x >> 5, c = x & 31;
                CP_ASYNC16(sb + (koff + row * 136 + c * 4) * 4,
                           g_WhBp + (size_t)(jn + row) * 128 + c * 4);
            }
            CP_COMMIT();
        }
        CP_WAITG(2);
        __syncthreads();                       // B0: K(tt) visible

        int2 na0 = *(const int2*)(arow0 + jn + jl0);
        int2 na1 = *(const int2*)(arow0 + jn + jl1);
        int2 na2 = *(const int2*)(arow1 + jn + jl0);
        int2 na3 = *(const int2*)(arow1 + jn + jl1);

        // ---- S = Whi . Whj^T (bf16 m16n8k16) ----
        float sS[2][4];
        sS[0][0] = sS[0][1] = sS[0][2] = sS[0][3] = 0.f;
        sS[1][0] = sS[1][1] = sS[1][2] = sS[1][3] = 0.f;
        const uint2* bK = (const uint2*)smu + (((tt & 1) ? OFF_K1 : OFF_K0) >> 1);
        const uint2* b0 = bK + (wn16 + g) * 68;
        const uint2* b1 = bK + (wn16 + 8 + g) * 68;
        #pragma unroll
        for (int gi = 0; gi < 16; gi++) {
            int o = gi * 4 + t;
            uint2 A0 = aR0[o], A1 = aR1[o];
            uint32_t A[4] = { A0.x, A1.x, A0.y, A1.y };
            uint2 Bv0 = b0[o];
            uint32_t B0[2] = { Bv0.x, Bv0.y };
            MMA16(sS[0], A, B0);
            uint2 Bv1 = b1[o];
            uint32_t B1[2] = { Bv1.x, Bv1.y };
            MMA16(sS[1], A, B1);
        }

        // ---- logits + row max ----
        float e[2][4];
        float rm0 = -INFINITY, rm1 = -INFINITY;
        #pragma unroll
        for (int nt = 0; nt < 2; nt++) {
            int jl = wn16 + nt * 8 + 2 * t;
            float2 uu = *(const float2*)(g_u + j0 + jl);
            float2 vv = *(const float2*)(g_v + j0 + jl);
            int2 a0 = pa[nt], a1 = pa[2 + nt];
            e[nt][0] = a0.x > 0 ? fmaf(cA, sS[nt][0], cB) + fmaf(pr0, uu.x, qr0 * vv.x) : NEG_MASK;
            e[nt][1] = a0.y > 0 ? fmaf(cA, sS[nt][1], cB) + fmaf(pr0, uu.y, qr0 * vv.y) : NEG_MASK;
            e[nt][2] = a1.x > 0 ? fmaf(cA, sS[nt][2], cB) + fmaf(pr1, uu.x, qr1 * vv.x) : NEG_MASK;
            e[nt][3] = a1.y > 0 ? fmaf(cA, sS[nt][3], cB) + fmaf(pr1, uu.y, qr1 * vv.y) : NEG_MASK;
            rm0 = fmaxf(rm0, fmaxf(e[nt][0], e[nt][1]));
            rm1 = fmaxf(rm1, fmaxf(e[nt][2], e[nt][3]));
        }
        pa[0] = na0; pa[1] = na1; pa[2] = na2; pa[3] = na3;
        rm0 = fmaxf(rm0, __shfl_xor_sync(~0u, rm0, 1));
        rm0 = fmaxf(rm0, __shfl_xor_sync(~0u, rm0, 2));
        rm1 = fmaxf(rm1, __shfl_xor_sync(~0u, rm1, 1));
        rm1 = fmaxf(rm1, __shfl_xor_sync(~0u, rm1, 2));
        if (t == 0) { sPart[wn * 64 + r0] = rm0; sPart[wn * 64 + r1] = rm1; }
        __syncthreads();                       // B1

        float mn0 = fmaxf(fmaxf(sPart[r0], sPart[64 + r0]),
                          fmaxf(sPart[128 + r0], sPart[192 + r0]));
        float mn1 = fmaxf(fmaxf(sPart[r1], sPart[64 + r1]),
                          fmaxf(sPart[128 + r1], sPart[192 + r1]));
        mn0 = fmaxf(m0, mn0);
        mn1 = fmaxf(m1, mn1);
        float sc0 = __expf(m0 - mn0), sc1 = __expf(m1 - mn1);
        m0 = mn0; m1 = mn1;
        lw0 *= sc0; lw1 *= sc1;
        if (wn == 0 && t == 0) { sSc[r0] = sc0; sSc[r1] = sc1; }

        // weights -> P (bf16x2, key-pair packed)
        #pragma unroll
        for (int nt = 0; nt < 2; nt++) {
            uint32_t pw0 = pack_bf16(__expf(e[nt][0] - m0), __expf(e[nt][1] - m0));
            uint32_t pw1 = pack_bf16(__expf(e[nt][2] - m1), __expf(e[nt][3] - m1));
            lw0 += __uint_as_float(pw0 << 16) + __uint_as_float(pw0 & 0xffff0000u);
            lw1 += __uint_as_float(pw1 << 16) + __uint_as_float(pw1 & 0xffff0000u);
            int col = wn * 8 + 2 * t + nt;
            sPu[r0 * 40 + col] = pw0;
            sPu[r1 * 40 + col] = pw1;
        }
        CP_WAITG(1);
        __syncthreads();                       // B2: P, sSc, T(tt) visible

        // ---- O rescale (PV mapping) ----
        {
            float s0 = sSc[wmO * 32 + g],      s1 = sSc[wmO * 32 + 8 + g];
            float s2 = sSc[wmO * 32 + 16 + g], s3 = sSc[wmO * 32 + 24 + g];
            if (fminf(fminf(s0, s1), fminf(s2, s3)) < 1.f) {
                #pragma unroll
                for (int nt = 0; nt < 4; nt++) {
                    O[0][nt][0] *= s0; O[0][nt][1] *= s0;
                    O[0][nt][2] *= s1; O[0][nt][3] *= s1;
                    O[1][nt][0] *= s2; O[1][nt][1] *= s2;
                    O[1][nt][2] *= s3; O[1][nt][3] *= s3;
                }
            }
        }

        // ---- O += P . V (bf16 hi/lo, u128 frags) ----
        #pragma unroll
        for (int ks = 0; ks < 4; ks++) {
            uint32_t A[2][4];
            #pragma unroll
            for (int mt = 0; mt < 2; mt++) {
                int rb = wmO * 32 + mt * 16;
                uint2 a0 = pP2[(rb + g) * 20 + ks * 4 + t];
                uint2 a1 = pP2[(rb + 8 + g) * 20 + ks * 4 + t];
                A[mt][0] = a0.x; A[mt][1] = a1.x; A[mt][2] = a0.y; A[mt][3] = a1.y;
            }
            #pragma unroll
            for (int nt = 0; nt < 4; nt++) {
                uint4 B = pT4[(wnO * 32 + nt * 8 + g) * 20 + ks * 4 + t];
                uint32_t Bh[2] = { B.x, B.y };
                uint32_t Bl[2] = { B.z, B.w };
                MMA16(O[0][nt], A[0], Bh);
                MMA16(O[0][nt], A[0], Bl);
                MMA16(O[1][nt], A[1], Bh);
                MMA16(O[1][nt], A[1], Bl);
            }
        }
        __syncthreads();                       // B3: PV reads done

        {   // prefetch T(tt+1)
            for (int x = tid; x < 256 * 16; x += 512) {
                int f = x >> 4, q = x & 15;
                CP_ASYNC16(sb + (OFF_T + f * 80 + q * 4) * 4,
                           (const char*)(g_WhT2 + (size_t)f * 2048 + (jn >> 4) * 4 + q));
            }
            CP_COMMIT();
        }
    }

    // ---- epilogue ----
    lw0 += __shfl_xor_sync(~0u, lw0, 1); lw0 += __shfl_xor_sync(~0u, lw0, 2);
    lw1 += __shfl_xor_sync(~0u, lw1, 1); lw1 += __shfl_xor_sync(~0u, lw1, 2);
    if (t == 0) { sPart[wn * 64 + r0] = lw0; sPart[wn * 64 + r1] = lw1; }
    __syncthreads();
    #pragma unroll
    for (int mt = 0; mt < 2; mt++) {
        int ra = wmO * 32 + mt * 16 + g;
        int rb = ra + 8;
        float inva = 1.f / (sPart[ra] + sPart[64 + ra] + sPart[128 + ra] + sPart[192 + ra]);
        float invb = 1.f / (sPart[rb] + sPart[64 + rb] + sPart[128 + rb] + sPart[192 + rb]);
        #pragma unroll
        for (int nt = 0; nt < 4; nt++) {
            int col = wnO * 32 + nt * 8 + 2 * t;
            float o0 = O[mt][nt][0] * inva, o1 = O[mt][nt][1] * inva;
            float o2 = O[mt][nt][2] * invb, o3 = O[mt][nt][3] * invb;
            o0 = o0 > 0.f ? o0 : expm1f(o0);
            o1 = o1 > 0.f ? o1 : expm1f(o1);
            o2 = o2 > 0.f ? o2 : expm1f(o2);
            o3 = o3 > 0.f ? o3 : expm1f(o3);
            *(float2*)(out + (size_t)(i0 + ra) * F_OUT + col) = make_float2(o0, o1);
            *(float2*)(out + (size_t)(i0 + rb) * F_OUT + col) = make_float2(o2, o3);
        }
    }
}

// ---------------- launcher ----------------
extern "C" void kernel_launch(void* const* d_in, const int* in_sizes, int n_in,
                              void* d_out, int out_size) {
    const float* h   = (const float*)d_in[0];
    const float* W   = (const float*)d_in[1];
    const float* Mui = (const float*)d_in[2];
    const int*   adj = (const int*)d_in[3];
    float* out = (float*)d_out;
    (void)in_sizes; (void)n_in; (void)out_size;

    cudaFuncSetAttribute(flash_mma, cudaFuncAttributeMaxDynamicSharedMemorySize,
                         SMEM_FLASH);

    mui_kernel<<<1, 32>>>(Mui);
    wh_gemm<<<dim3(2, 64), 256>>>(h, W);
    node_prep<<<N_NODES / 256, 256>>>();
    transpose_pack<<<dim3(8, 128), 256>>>();
    flash_mma<<<N_NODES / 64, 512, SMEM_FLASH>>>(adj, out);
}

// round 16
// speedup vs baseline: 1.6147x; 1.1917x over previous
#include <cuda_runtime.h>
#include <math.h>
#include <stdint.h>
#include <cuda_bf16.h>
#include <cuda_fp16.h>

#define N_NODES 8192
#define F_IN    512
#define F_OUT   256
#define NEG_MASK (-9e15f)

__device__ float    g_Wh[N_NODES * F_OUT];           // exact f32
__device__ uint32_t g_WhBp[N_NODES * (F_OUT / 2)];   // bf16x2 frag-packed (S)
__device__ uint2    g_WhT2[F_OUT * 2048];            // V^T fp16x2, frag-packed (PV)
__device__ float g_u[N_NODES], g_v[N_NODES], g_p[N_NODES], g_q[N_NODES];
__device__ float g_coef[4];

__device__ __forceinline__ uint32_t smem_u32(const void* p) {
    uint32_t a;
    asm("{ .reg .u64 t; cvta.to.shared.u64 t, %1; cvt.u32.u64 %0, t; }" : "=r"(a) : "l"(p));
    return a;
}
__device__ __forceinline__ uint32_t pack_bf16(float lo, float hi) {
    uint32_t r; asm("cvt.rn.bf16x2.f32 %0, %1, %2;" : "=r"(r) : "f"(hi), "f"(lo)); return r;
}
__device__ __forceinline__ uint32_t pack_f16(float lo, float hi) {
    uint32_t r; asm("cvt.rn.f16x2.f32 %0, %1, %2;" : "=r"(r) : "f"(hi), "f"(lo)); return r;
}
#define MMA16B(c, A, B) \
    asm volatile("mma.sync.aligned.m16n8k16.row.col.f32.bf16.bf16.f32 " \
        "{%0,%1,%2,%3},{%4,%5,%6,%7},{%8,%9},{%0,%1,%2,%3};" \
        : "+f"((c)[0]), "+f"((c)[1]), "+f"((c)[2]), "+f"((c)[3]) \
        : "r"((A)[0]), "r"((A)[1]), "r"((A)[2]), "r"((A)[3]), \
          "r"((B)[0]), "r"((B)[1]))
#define MMA16H(c, A, B) \
    asm volatile("mma.sync.aligned.m16n8k16.row.col.f32.f16.f16.f32 " \
        "{%0,%1,%2,%3},{%4,%5,%6,%7},{%8,%9},{%0,%1,%2,%3};" \
        : "+f"((c)[0]), "+f"((c)[1]), "+f"((c)[2]), "+f"((c)[3]) \
        : "r"((A)[0]), "r"((A)[1]), "r"((A)[2]), "r"((A)[3]), \
          "r"((B)[0]), "r"((B)[1]))
#define CP_ASYNC16(saddr, g) \
    asm volatile("cp.async.cg.shared.global [%0], [%1], 16;" :: "r"(saddr), "l"(g))
#define CP_COMMIT() asm volatile("cp.async.commit_group;")
#define CP_WAITG(n) asm volatile("cp.async.wait_group %0;" :: "n"(n))

// ---------------- kernel 1: softmax(Mui) ----------------
__global__ void mui_kernel(const float* __restrict__ Mui) {
    if (threadIdx.x == 0 && blockIdx.x == 0) {
        float m = -INFINITY;
        for (int i = 0; i < 6; i++) m = fmaxf(m, Mui[i]);
        float w[6], s = 0.f;
        for (int i = 0; i < 6; i++) { w[i] = expf(Mui[i] - m); s += w[i]; }
        float inv = 1.f / s;
        for (int i = 0; i < 6; i++) w[i] *= inv;
        g_coef[0] = w[0] + w[1] + w[2] + w[3];
        g_coef[1] = 0.5f * (w[0] + w[1]) + (w[2] + w[3]);
        g_coef[2] = 256.0f * w[4];
        g_coef[3] = 256.0f * w[5];
    }
}

// ---------------- kernel 2: Wh = h @ W; f32 + bf16 frag-packed ----------------
__global__ __launch_bounds__(256) void wh_gemm(const float* __restrict__ h,
                                               const float* __restrict__ W) {
    __shared__ float sA[16][128];
    __shared__ float sB[16][128];
    const int tid = threadIdx.x, tx = tid & 15, ty = tid >> 4;
    const int n0 = blockIdx.x * 128, m0 = blockIdx.y * 128;
    float acc[8][8];
    #pragma unroll
    for (int i = 0; i < 8; i++)
        #pragma unroll
        for (int j = 0; j < 8; j++) acc[i][j] = 0.f;
    for (int k0 = 0; k0 < F_IN; k0 += 16) {
        #pragma unroll
        for (int l = 0; l < 2; l++) {
            int idx = tid + l * 256;
            int row = idx >> 2, kq = idx & 3;
            float4 a = *(const float4*)&h[(size_t)(m0 + row) * F_IN + k0 + kq * 4];
            sA[kq * 4 + 0][row] = a.x; sA[kq * 4 + 1][row] = a.y;
            sA[kq * 4 + 2][row] = a.z; sA[kq * 4 + 3][row] = a.w;
            int rowb = idx >> 5, cq = idx & 31;
            *(float4*)&sB[rowb][cq * 4] =
                *(const float4*)&W[(size_t)(k0 + rowb) * F_OUT + n0 + cq * 4];
        }
        __syncthreads();
        #pragma unroll
        for (int k = 0; k < 16; k++) {
            float a[8], b[8];
            *(float4*)(a) = *(float4*)&sA[k][ty * 8];
            *(float4*)(a + 4) = *(float4*)&sA[k][ty * 8 + 4];
            *(float4*)(b) = *(float4*)&sB[k][tx * 8];
            *(float4*)(b + 4) = *(float4*)&sB[k][tx * 8 + 4];
            #pragma unroll
            for (int i = 0; i < 8; i++)
                #pragma unroll
                for (int j = 0; j < 8; j++) acc[i][j] = fmaf(a[i], b[j], acc[i][j]);
        }
        __syncthreads();
    }
    const int base = n0 + tx * 8;
    #pragma unroll
    for (int i = 0; i < 8; i++) {
        size_t rw = (size_t)(m0 + ty * 8 + i);
        *(float4*)&g_Wh[rw * F_OUT + base]     = *(float4*)&acc[i][0];
        *(float4*)&g_Wh[rw * F_OUT + base + 4] = *(float4*)&acc[i][4];
        #pragma unroll
        for (int w2 = 0; w2 < 4; w2++) {
            int f = base + 2 * w2;
            int gi = f >> 4, wl = (f >> 1) & 7;
            int pos = (wl & 3) * 2 + (wl >> 2);
            g_WhBp[rw * 128 + gi * 8 + pos] = pack_bf16(acc[i][2 * w2], acc[i][2 * w2 + 1]);
        }
    }
}

// ---------------- kernel 3: per-node factors ----------------
__global__ void node_prep() {
    int i = blockIdx.x * blockDim.x + threadIdx.x;
    if (i < N_NODES) {
        float wh1 = g_Wh[(size_t)i * F_OUT + 1];
        float t1 = wh1 * wh1;
        g_u[i] = expf(0.5f * t1);
        g_v[i] = expf(t1);
        g_p[i] = g_coef[2] * expf(-0.5f * t1);
        g_q[i] = g_coef[3] * expf(-t1);
    }
}

// ---------------- kernel 3b: V^T fp16x2 frag-packed ----------------
// For feature f, 16-key group gi: thread-word t uint2 = { f16x2(k=2t,2t+1), f16x2(k=2t+8,2t+9) }
__global__ __launch_bounds__(256) void transpose_pack() {
    __shared__ float tile[64][33];
    const int f0 = blockIdx.x * 32, j0 = blockIdx.y * 64;
    const int tid = threadIdx.x;
    #pragma unroll
    for (int i = 0; i < 2; i++) {
        int idx = tid + i * 256;
        int row = idx >> 3, c4 = idx & 7;
        float4 a = *(const float4*)&g_Wh[(size_t)(j0 + row) * F_OUT + f0 + c4 * 4];
        tile[row][c4 * 4 + 0] = a.x; tile[row][c4 * 4 + 1] = a.y;
        tile[row][c4 * 4 + 2] = a.z; tile[row][c4 * 4 + 3] = a.w;
    }
    __syncthreads();
    #pragma unroll
    for (int i = 0; i < 2; i++) {
        int idx = tid + i * 256;
        int f = idx >> 4, gi = (idx >> 2) & 3, t = idx & 3;
        int k0 = gi * 16 + 2 * t;
        uint2 o;
        o.x = pack_f16(tile[k0][f],     tile[k0 + 1][f]);
        o.y = pack_f16(tile[k0 + 8][f], tile[k0 + 9][f]);
        g_WhT2[(size_t)(f0 + f) * 2048 + ((j0 >> 4) + gi) * 4 + t] = o;
    }
}

// ---------------- kernel 4: flash (bf16 S, fp16 PV) ----------------
// S warps: wm=wid&3 (16 rows), wn=wid>>2 (16 S-cols).
// PV warps: wmO=wid&1 (32 rows), wnO=wid>>1 (32 O-cols).
#define OFF_WHI  0        // 64 x 136 u32
#define OFF_K0   8704
#define OFF_K1   17408
#define OFF_T    26112    // 256 x 40 u32 (u64 stride 20)
#define OFF_P    36352    // 64 x 40 u32 (fp16x2, u64 stride 20)
#define OFF_PART 38912    // 256 f32
#define OFF_SC   39168    // 64 f32
#define SMEM_FLASH (39232 * 4)

__global__ __launch_bounds__(512, 1) void flash_mma(const int* __restrict__ adj,
                                                    float* __restrict__ out) {
    extern __shared__ float sm[];
    uint32_t* smu = (uint32_t*)sm;
    const uint32_t sb = smem_u32(sm);
    float* sPart = sm + OFF_PART;
    float* sSc   = sm + OFF_SC;

    const int tid = threadIdx.x, lane = tid & 31, wid = tid >> 5;
    const int wm = wid & 3, wn = wid >> 2;            // S mapping
    const int wmO = wid & 1, wnO = wid >> 1;          // PV mapping
    const int g = lane >> 2, t = lane & 3;
    const int i0 = blockIdx.x * 64;
    const int r0 = wm * 16 + g, r1 = r0 + 8;
    const int wn16 = wn * 16;

    // stage Whi (bf16 packed)
    for (int x = tid; x < 64 * 32; x += 512) {
        int row = x >> 5, c = x & 31;
        *(uint4*)(smu + OFF_WHI + row * 136 + c * 4) =
            *(const uint4*)(g_WhBp + (size_t)(i0 + row) * 128 + c * 4);
    }
    // prefetch K(0), T(0)
    for (int x = tid; x < 64 * 32; x += 512) {
        int row = x >> 5, c = x & 31;
        CP_ASYNC16(sb + (OFF_K0 + row * 136 + c * 4) * 4,
                   g_WhBp + (size_t)row * 128 + c * 4);
    }
    CP_COMMIT();
    for (int x = tid; x < 256 * 8; x += 512) {
        int f = x >> 3, q = x & 7;
        CP_ASYNC16(sb + (OFF_T + f * 40 + q * 4) * 4,
                   (const char*)(g_WhT2 + (size_t)f * 2048 + q * 2));
    }
    CP_COMMIT();

    const float cA = g_coef[0], cB = g_coef[1];
    const float pr0 = g_p[i0 + r0], qr0 = g_q[i0 + r0];
    const float pr1 = g_p[i0 + r1], qr1 = g_q[i0 + r1];
    const int* arow0 = adj + (size_t)(i0 + r0) * N_NODES;
    const int* arow1 = adj + (size_t)(i0 + r1) * N_NODES;
    const int jl0 = wn16 + 2 * t, jl1 = wn16 + 8 + 2 * t;

    int2 pa[4];
    pa[0] = *(const int2*)(arow0 + jl0);
    pa[1] = *(const int2*)(arow0 + jl1);
    pa[2] = *(const int2*)(arow1 + jl0);
    pa[3] = *(const int2*)(arow1 + jl1);

    float O[2][4][4];
    #pragma unroll
    for (int mt = 0; mt < 2; mt++)
        #pragma unroll
        for (int nt = 0; nt < 4; nt++)
            #pragma unroll
            for (int c = 0; c < 4; c++) O[mt][nt][c] = 0.f;
    float lw0 = 0.f, lw1 = 0.f, m0 = -INFINITY, m1 = -INFINITY;

    const uint2* aR0 = (const uint2*)smu + (OFF_WHI >> 1) + r0 * 68;
    const uint2* aR1 = (const uint2*)smu + (OFF_WHI >> 1) + r1 * 68;
    const uint2* pP2 = (const uint2*)(smu + OFF_P);
    const uint2* pT2 = (const uint2*)(smu + OFF_T);
    uint32_t* sPu = smu + OFF_P;

    for (int tt = 0; tt < 128; tt++) {
        const int j0 = tt * 64;
        const int jn = ((tt + 1) & 127) * 64;
        {   // prefetch K(tt+1)
            int koff = ((tt + 1) & 1) ? OFF_K1 : OFF_K0;
            for (int x = tid; x < 64 * 32; x += 512) {
                int row = x >> 5, c = x & 31;
                CP_ASYNC16(sb + (koff + row * 136 + c * 4) * 4,
                           g_WhBp + (size_t)(jn + row) * 128 + c * 4);
            }
            CP_COMMIT();
        }
        CP_WAITG(2);
        __syncthreads();                       // B0: K(tt) visible

        int2 na0 = *(const int2*)(arow0 + jn + jl0);
        int2 na1 = *(const int2*)(arow0 + jn + jl1);
        int2 na2 = *(const int2*)(arow1 + jn + jl0);
        int2 na3 = *(const int2*)(arow1 + jn + jl1);

        // ---- S = Whi . Whj^T (bf16 m16n8k16) ----
        float sS[2][4];
        sS[0][0] = sS[0][1] = sS[0][2] = sS[0][3] = 0.f;
        sS[1][0] = sS[1][1] = sS[1][2] = sS[1][3] = 0.f;
        const uint2* bK = (const uint2*)smu + (((tt & 1) ? OFF_K1 : OFF_K0) >> 1);
        const uint2* b0 = bK + (wn16 + g) * 68;
        const uint2* b1 = bK + (wn16 + 8 + g) * 68;
        #pragma unroll
        for (int gi = 0; gi < 16; gi++) {
            int o = gi * 4 + t;
            uint2 A0 = aR0[o], A1 = aR1[o];
            uint32_t A[4] = { A0.x, A1.x, A0.y, A1.y };
            uint2 Bv0 = b0[o];
            uint32_t B0[2] = { Bv0.x, Bv0.y };
            MMA16B(sS[0], A, B0);
            uint2 Bv1 = b1[o];
            uint32_t B1[2] = { Bv1.x, Bv1.y };
            MMA16B(sS[1], A, B1);
        }

        // ---- logits + row max ----
        float e[2][4];
        float rm0 = -INFINITY, rm1 = -INFINITY;
        #pragma unroll
        for (int nt = 0; nt < 2; nt++) {
            int jl = wn16 + nt * 8 + 2 * t;
            float2 uu = *(const float2*)(g_u + j0 + jl);
            float2 vv = *(const float2*)(g_v + j0 + jl);
            int2 a0 = pa[nt], a1 = pa[2 + nt];
            e[nt][0] = a0.x > 0 ? fmaf(cA, sS[nt][0], cB) + fmaf(pr0, uu.x, qr0 * vv.x) : NEG_MASK;
            e[nt][1] = a0.y > 0 ? fmaf(cA, sS[nt][1], cB) + fmaf(pr0, uu.y, qr0 * vv.y) : NEG_MASK;
            e[nt][2] = a1.x > 0 ? fmaf(cA, sS[nt][2], cB) + fmaf(pr1, uu.x, qr1 * vv.x) : NEG_MASK;
            e[nt][3] = a1.y > 0 ? fmaf(cA, sS[nt][3], cB) + fmaf(pr1, uu.y, qr1 * vv.y) : NEG_MASK;
            rm0 = fmaxf(rm0, fmaxf(e[nt][0], e[nt][1]));
            rm1 = fmaxf(rm1, fmaxf(e[nt][2], e[nt][3]));
        }
        pa[0] = na0; pa[1] = na1; pa[2] = na2; pa[3] = na3;
        rm0 = fmaxf(rm0, __shfl_xor_sync(~0u, rm0, 1));
        rm0 = fmaxf(rm0, __shfl_xor_sync(~0u, rm0, 2));
        rm1 = fmaxf(rm1, __shfl_xor_sync(~0u, rm1, 1));
        rm1 = fmaxf(rm1, __shfl_xor_sync(~0u, rm1, 2));
        if (t == 0) { sPart[wn * 64 + r0] = rm0; sPart[wn * 64 + r1] = rm1; }
        __syncthreads();                       // B1

        float mn0 = fmaxf(fmaxf(sPart[r0], sPart[64 + r0]),
                          fmaxf(sPart[128 + r0], sPart[192 + r0]));
        float mn1 = fmaxf(fmaxf(sPart[r1], sPart[64 + r1]),
                          fmaxf(sPart[128 + r1], sPart[192 + r1]));
        mn0 = fmaxf(m0, mn0);
        mn1 = fmaxf(m1, mn1);
        float sc0 = __expf(m0 - mn0), sc1 = __expf(m1 - mn1);
        m0 = mn0; m1 = mn1;
        lw0 *= sc0; lw1 *= sc1;
        if (wn == 0 && t == 0) { sSc[r0] = sc0; sSc[r1] = sc1; }

        // weights -> P (fp16x2, key-pair packed)
        #pragma unroll
        for (int nt = 0; nt < 2; nt++) {
            float w00 = __expf(e[nt][0] - m0), w01 = __expf(e[nt][1] - m0);
            float w10 = __expf(e[nt][2] - m1), w11 = __expf(e[nt][3] - m1);
            uint32_t pw0 = pack_f16(w00, w01);
            uint32_t pw1 = pack_f16(w10, w11);
            float2 f0 = __half22float2(*(__half2*)&pw0);
            float2 f1 = __half22float2(*(__half2*)&pw1);
            lw0 += f0.x + f0.y;
            lw1 += f1.x + f1.y;
            int col = wn * 8 + 2 * t + nt;
            sPu[r0 * 40 + col] = pw0;
            sPu[r1 * 40 + col] = pw1;
        }
        CP_WAITG(1);
        __syncthreads();                       // B2: P, sSc, T(tt) visible

        // ---- O rescale (PV mapping) ----
        {
            float s0 = sSc[wmO * 32 + g],      s1 = sSc[wmO * 32 + 8 + g];
            float s2 = sSc[wmO * 32 + 16 + g], s3 = sSc[wmO * 32 + 24 + g];
            if (fminf(fminf(s0, s1), fminf(s2, s3)) < 1.f) {
                #pragma unroll
                for (int nt = 0; nt < 4; nt++) {
                    O[0][nt][0] *= s0; O[0][nt][1] *= s0;
                    O[0][nt][2] *= s1; O[0][nt][3] *= s1;
                    O[1][nt][0] *= s2; O[1][nt][1] *= s2;
                    O[1][nt][2] *= s3; O[1][nt][3] *= s3;
                }
            }
        }

        // ---- O += P . V (fp16, LDS.64 frags) ----
        #pragma unroll
        for (int ks = 0; ks < 4; ks++) {
            uint32_t A[2][4];
            #pragma unroll
            for (int mt = 0; mt < 2; mt++) {
                int rb = wmO * 32 + mt * 16;
                uint2 a0 = pP2[(rb + g) * 20 + ks * 4 + t];
                uint2 a1 = pP2[(rb + 8 + g) * 20 + ks * 4 + t];
                A[mt][0] = a0.x; A[mt][1] = a1.x; A[mt][2] = a0.y; A[mt][3] = a1.y;
            }
            #pragma unroll
            for (int nt = 0; nt < 4; nt++) {
                uint2 B = pT2[(wnO * 32 + nt * 8 + g) * 20 + ks * 4 + t];
                uint32_t Bv[2] = { B.x, B.y };
                MMA16H(O[0][nt], A[0], Bv);
                MMA16H(O[1][nt], A[1], Bv);
            }
        }
        __syncthreads();                       // B3: PV reads done

        {   // prefetch T(tt+1)
            for (int x = tid; x < 256 * 8; x += 512) {
                int f = x >> 3, q = x & 7;
                CP_ASYNC16(sb + (OFF_T + f * 40 + q * 4) * 4,
                           (const char*)(g_WhT2 + (size_t)f * 2048 + (jn >> 4) * 4 + q * 2));
            }
            CP_COMMIT();
        }
    }

    // ---- epilogue ----
    lw0 += __shfl_xor_sync(~0u, lw0, 1); lw0 += __shfl_xor_sync(~0u, lw0, 2);
    lw1 += __shfl_xor_sync(~0u, lw1, 1); lw1 += __shfl_xor_sync(~0u, lw1, 2);
    if (t == 0) { sPart[wn * 64 + r0] = lw0; sPart[wn * 64 + r1] = lw1; }
    __syncthreads();
    #pragma unroll
    for (int mt = 0; mt < 2; mt++) {
        int ra = wmO * 32 + mt * 16 + g;
        int rb = ra + 8;
        float inva = 1.f / (sPart[ra] + sPart[64 + ra] + sPart[128 + ra] + sPart[192 + ra]);
        float invb = 1.f / (sPart[rb] + sPart[64 + rb] + sPart[128 + rb] + sPart[192 + rb]);
        #pragma unroll
        for (int nt = 0; nt < 4; nt++) {
            int col = wnO * 32 + nt * 8 + 2 * t;
            float o0 = O[mt][nt][0] * inva, o1 = O[mt][nt][1] * inva;
            float o2 = O[mt][nt][2] * invb, o3 = O[mt][nt][3] * invb;
            o0 = o0 > 0.f ? o0 : expm1f(o0);
            o1 = o1 > 0.f ? o1 : expm1f(o1);
            o2 = o2 > 0.f ? o2 : expm1f(o2);
            o3 = o3 > 0.f ? o3 : expm1f(o3);
            *(float2*)(out + (size_t)(i0 + ra) * F_OUT + col) = make_float2(o0, o1);
            *(float2*)(out + (size_t)(i0 + rb) * F_OUT + col) = make_float2(o2, o3);
        }
    }
}

// ---------------- launcher ----------------
extern "C" void kernel_launch(void* const* d_in, const int* in_sizes, int n_in,
                              void* d_out, int out_size) {
    const float* h   = (const float*)d_in[0];
    const float* W   = (const float*)d_in[1];
    const float* Mui = (const float*)d_in[2];
    const int*   adj = (const int*)d_in[3];
    float* out = (float*)d_out;
    (void)in_sizes; (void)n_in; (void)out_size;

    cudaFuncSetAttribute(flash_mma, cudaFuncAttributeMaxDynamicSharedMemorySize,
                         SMEM_FLASH);

    mui_kernel<<<1, 32>>>(Mui);
    wh_gemm<<<dim3(2, 64), 256>>>(h, W);
    node_prep<<<N_NODES / 256, 256>>>();
    transpose_pack<<<dim3(8, 128), 256>>>();
    flash_mma<<<N_NODES / 64, 512, SMEM_FLASH>>>(adj, out);
}